// round 13
// baseline (speedup 1.0000x reference)
#include <cuda_runtime.h>
#include <cuda_bf16.h>
#include <math.h>

#define Hdim 1024
#define Ldim 10
#define Vdim 50257
#define MAXNB5 1536
#define NB7 ((Vdim + 255) / 256)                          // 197
#define ROWS2 7      // k2: rows per block (147*7 >= 1024)
#define UPB3 2       // k3: units per block (512 blocks)

// ---- scratch (no allocations allowed) ----
__device__ __align__(16) float g_scores[Ldim];
__device__ __align__(16) float g_x[Hdim];
__device__ __align__(16) float g_hnew[Hdim];
__device__ __align__(16) float g_logits[Vdim];
__device__ float g_pmax[MAXNB5];
__device__ float g_psum[MAXNB5];

__device__ __forceinline__ float warp_sum(float s) {
#pragma unroll
    for (int o = 16; o; o >>= 1) s += __shfl_down_sync(0xffffffffu, s, o);
    return s;
}

__device__ __forceinline__ void lse_merge(float& m, float& s, float m2, float s2) {
    if (m2 > m) { s = s * expf(m - m2) + s2; m = m2; }
    else if (s2 > 0.f) { s += s2 * expf(m2 - m); }
}

__device__ __forceinline__ void l2_prefetch(const void* p) {
    asm volatile("prefetch.global.L2 [%0];" :: "l"(p));
}

__device__ __forceinline__ float dot4(float4 a, float4 b) {
    return a.x * b.x + a.y * b.y + a.z * b.z + a.w * b.w;
}

// K1: attention scores only. 10 blocks x 256 threads; inputs only -> no gridsync.
__global__ __launch_bounds__(256) void k1_scores(const int* __restrict__ inp,
                                                 const float* __restrict__ hidden,
                                                 const float* __restrict__ emb,
                                                 const float* __restrict__ attn_W,
                                                 const float* __restrict__ attn_b) {
    cudaTriggerProgrammaticLaunchCompletion();
    __shared__ float red[8];
    int l = blockIdx.x;
    int tid = threadIdx.x, warp = tid >> 5, lane = tid & 31;
    int tok = inp[0];
    const float4* erow = (const float4*)(emb + (size_t)tok * Hdim);
    const float4* h4 = (const float4*)hidden;
    const float4* wr = (const float4*)(attn_W + (size_t)l * 2 * Hdim);
    float4 w0 = __ldcs(wr + tid);
    float4 w1 = __ldcs(wr + 256 + tid);
    float s = dot4(w0, erow[tid]) + dot4(w1, h4[tid]);
    s = warp_sum(s);
    if (lane == 0) red[warp] = s;
    __syncthreads();
    if (tid == 0) {
        float v = red[0] + red[1] + red[2] + red[3]
                + red[4] + red[5] + red[6] + red[7];
        g_scores[l] = v + attn_b[l];
    }
}

// K2: 147 blocks x 512. Each block: softmax (regs), xcat (smem), 7 comb rows.
__global__ __launch_bounds__(512) void k2_comb(const float* __restrict__ comb_W,
                                               const float* __restrict__ comb_b,
                                               const int* __restrict__ inp,
                                               const float* __restrict__ emb,
                                               const float* __restrict__ enc,
                                               float* __restrict__ out, int out_size) {
    __shared__ __align__(16) float s_xcat[2 * Hdim];
    int tid = threadIdx.x, warp = tid >> 5, lane = tid & 31;
    int r0 = blockIdx.x * ROWS2;

    for (int i = tid; i < ROWS2 * 64; i += 512) {
        int r = r0 + i / 64;
        if (r < Hdim)
            l2_prefetch((const char*)(comb_W + (size_t)r * 2 * Hdim) + (i % 64) * 128);
    }
    if (blockIdx.x < 8)
        for (int i = tid; i < 320; i += 512)
            l2_prefetch((const char*)enc + i * 128);
    int tok = inp[0];
    if (tid < 256)
        ((float4*)s_xcat)[tid] = ((const float4*)(emb + (size_t)tok * Hdim))[tid];

    cudaTriggerProgrammaticLaunchCompletion();
    cudaGridDependencySynchronize();

    float wl[Ldim];
    {
        float sc[Ldim];
#pragma unroll
        for (int l = 0; l < Ldim; l++) sc[l] = g_scores[l];
        float m = sc[0];
#pragma unroll
        for (int l = 1; l < Ldim; l++) m = fmaxf(m, sc[l]);
        float ssum = 0.f;
#pragma unroll
        for (int l = 0; l < Ldim; l++) { wl[l] = expf(sc[l] - m); ssum += wl[l]; }
        float inv = 1.f / ssum;
#pragma unroll
        for (int l = 0; l < Ldim; l++) wl[l] *= inv;
    }
    if (blockIdx.x == 0 && tid < Ldim && out_size >= Vdim + Hdim + Ldim)
        out[Vdim + Hdim + tid] = wl[tid];

    if (tid < 256) {
        const float4* e4 = (const float4*)enc;
        float4 a = make_float4(0.f, 0.f, 0.f, 0.f);
#pragma unroll
        for (int l = 0; l < Ldim; l++) {
            float4 e = __ldg(e4 + l * 256 + tid);
            a.x += wl[l] * e.x; a.y += wl[l] * e.y;
            a.z += wl[l] * e.z; a.w += wl[l] * e.w;
        }
        ((float4*)s_xcat)[256 + tid] = a;
    }
    __syncthreads();

    if (warp < ROWS2) {
        int r = r0 + warp;
        if (r < Hdim) {
            const float4* wr = (const float4*)(comb_W + (size_t)r * 2 * Hdim);
            const float4* xc = (const float4*)s_xcat;
            float s = 0.f;
#pragma unroll
            for (int k = 0; k < 16; k++) {
                int idx = lane + 32 * k;
                s += dot4(__ldcs(wr + idx), xc[idx]);
            }
            s = warp_sum(s);
            if (lane == 0) g_x[r] = fmaxf(s + comb_b[r], 0.f);
        }
    }
}

// K3: 512 blocks x 256 threads, 2 units each. Pre-sync L2-prefetch of all rows.
__global__ __launch_bounds__(256) void k3_gru(const float* __restrict__ hidden,
                                              const float* __restrict__ wih,
                                              const float* __restrict__ whh,
                                              const float* __restrict__ bih,
                                              const float* __restrict__ bhh,
                                              float* __restrict__ out, int out_size) {
    __shared__ float red[6][8];
    int u0 = blockIdx.x * UPB3;
    int tid = threadIdx.x, warp = tid >> 5, lane = tid & 31;

    for (int i = tid; i < UPB3 * 6 * 32; i += 256) {
        int uu = i / 192;
        int rem = i % 192;
        int row6 = rem / 32;
        int line = rem % 32;
        int u = u0 + uu;
        const float* base;
        if (row6 < 3) base = wih + (size_t)(u + row6 * Hdim) * Hdim;
        else          base = whh + (size_t)(u + (row6 - 3) * Hdim) * Hdim;
        l2_prefetch((const char*)base + line * 128);
    }
    float4 hv = ((const float4*)hidden)[tid];

    cudaTriggerProgrammaticLaunchCompletion();
    cudaGridDependencySynchronize();

    float4 xv = ((const float4*)g_x)[tid];

#pragma unroll
    for (int j = 0; j < UPB3; j++) {
        int u = u0 + j;
        const float4* wir = (const float4*)(wih + (size_t)u * Hdim);
        const float4* wiz = (const float4*)(wih + (size_t)(u + Hdim) * Hdim);
        const float4* win = (const float4*)(wih + (size_t)(u + 2 * Hdim) * Hdim);
        const float4* whr = (const float4*)(whh + (size_t)u * Hdim);
        const float4* whz = (const float4*)(whh + (size_t)(u + Hdim) * Hdim);
        const float4* whn = (const float4*)(whh + (size_t)(u + 2 * Hdim) * Hdim);
        float s0 = dot4(__ldcs(wir + tid), xv);
        float s1 = dot4(__ldcs(wiz + tid), xv);
        float s2 = dot4(__ldcs(win + tid), xv);
        float s3 = dot4(__ldcs(whr + tid), hv);
        float s4 = dot4(__ldcs(whz + tid), hv);
        float s5 = dot4(__ldcs(whn + tid), hv);
        s0 = warp_sum(s0); s1 = warp_sum(s1); s2 = warp_sum(s2);
        s3 = warp_sum(s3); s4 = warp_sum(s4); s5 = warp_sum(s5);
        if (lane == 0) {
            red[0][warp] = s0; red[1][warp] = s1; red[2][warp] = s2;
            red[3][warp] = s3; red[4][warp] = s4; red[5][warp] = s5;
        }
        __syncthreads();
        if (tid == 0) {
            float g[6];
#pragma unroll
            for (int gi = 0; gi < 6; gi++) {
                float acc = 0.f;
#pragma unroll
                for (int w = 0; w < 8; w++) acc += red[gi][w];
                g[gi] = acc;
            }
            float r = 1.f / (1.f + expf(-((g[0] + bih[u]) + (g[3] + bhh[u]))));
            float z = 1.f / (1.f + expf(-((g[1] + bih[Hdim + u]) + (g[4] + bhh[Hdim + u]))));
            float n = tanhf((g[2] + bih[2 * Hdim + u]) + r * (g[5] + bhh[2 * Hdim + u]));
            float hn = (1.f - z) * n + z * hidden[u];
            g_hnew[u] = hn;
            if (out_size >= Vdim + Hdim) out[Vdim + u] = hn;
        }
        __syncthreads();
    }
}

// K5: persistent, 256 thr, warp-per-row strided; NEXT-row full prefetch each
// iteration (32 lanes x 1 line = whole 4KB row) so current-row loads hit L2
// and the warp_sum/lse dependent chain no longer gates memory issue.
__global__ __launch_bounds__(256) void k5_logits(const float* __restrict__ outW,
                                                 const float* __restrict__ outb) {
    __shared__ __align__(16) float sh[Hdim];
    __shared__ float sm[8], ss[8];
    int tid = threadIdx.x, warp = tid >> 5, lane = tid & 31;

    int per = (Vdim + gridDim.x - 1) / gridDim.x;
    int start = blockIdx.x * per;
    int end = start + per; if (end > Vdim) end = Vdim;

    // warm this warp's first row while predecessors run
    if (start + warp < end)
        l2_prefetch((const char*)(outW + (size_t)(start + warp) * Hdim) + lane * 128);

    cudaTriggerProgrammaticLaunchCompletion();
    cudaGridDependencySynchronize();

    sh[tid] = g_hnew[tid];
    sh[tid + 256] = g_hnew[tid + 256];
    sh[tid + 512] = g_hnew[tid + 512];
    sh[tid + 768] = g_hnew[tid + 768];
    __syncthreads();
    const float4* hh = (const float4*)sh;

    float m = -INFINITY, ssum = 0.f;
    for (int r = start + warp; r < end; r += 8) {
        int rn = r + 8;
        if (rn < end)       // prefetch NEXT row (full 4KB via 32 lanes)
            l2_prefetch((const char*)(outW + (size_t)rn * Hdim) + lane * 128);
        const float4* wr = (const float4*)(outW + (size_t)r * Hdim);
        float s = 0.f;
#pragma unroll
        for (int k = 0; k < 8; k++) {
            int idx = lane + 32 * k;
            s += dot4(__ldcs(wr + idx), hh[idx]);
        }
        s = warp_sum(s);
        if (lane == 0) {
            float lg = s + outb[r];
            g_logits[r] = lg;
            lse_merge(m, ssum, lg, 1.f);
        }
    }
    if (lane == 0) { sm[warp] = m; ss[warp] = ssum; }
    __syncthreads();
    if (tid == 0) {
        float gm = -INFINITY, gs = 0.f;
#pragma unroll
        for (int w = 0; w < 8; w++) lse_merge(gm, gs, sm[w], ss[w]);
        g_pmax[blockIdx.x] = gm;
        g_psum[blockIdx.x] = gs;
    }
}

// K67: global logsumexp reduce (redundant per block) + output write.
__global__ __launch_bounds__(256) void k67_write(float* __restrict__ out, int nb5) {
    cudaGridDependencySynchronize();
    __shared__ float sm[256], ss[256];
    int tid = threadIdx.x;
    float m = -INFINITY, s = 0.f;
    for (int b = tid; b < nb5; b += 256)
        lse_merge(m, s, g_pmax[b], g_psum[b]);
    sm[tid] = m; ss[tid] = s;
    __syncthreads();
#pragma unroll
    for (int o = 128; o; o >>= 1) {
        if (tid < o) lse_merge(sm[tid], ss[tid], sm[tid + o], ss[tid + o]);
        __syncthreads();
    }
    __shared__ float shift;
    if (tid == 0) shift = sm[0] + logf(ss[0]);
    __syncthreads();
    int v = blockIdx.x * 256 + tid;
    if (v < Vdim) out[v] = g_logits[v] - shift;
}

static inline void launch_pdl(void* func, dim3 grid, dim3 block, void** args) {
    cudaLaunchAttribute attr[1];
    attr[0].id = cudaLaunchAttributeProgrammaticStreamSerialization;
    attr[0].val.programmaticStreamSerializationAllowed = 1;
    cudaLaunchConfig_t cfg = {};
    cfg.gridDim = grid;
    cfg.blockDim = block;
    cfg.dynamicSmemBytes = 0;
    cfg.stream = 0;
    cfg.attrs = attr;
    cfg.numAttrs = 1;
    cudaLaunchKernelExC(&cfg, func, args);
}

extern "C" void kernel_launch(void* const* d_in, const int* in_sizes, int n_in,
                              void* d_out, int out_size) {
    const int*   inp    = (const int*)  d_in[0];
    const float* hidden = (const float*)d_in[1];
    const float* enc    = (const float*)d_in[2];
    const float* emb    = (const float*)d_in[3];
    const float* attn_W = (const float*)d_in[4];
    const float* attn_b = (const float*)d_in[5];
    const float* comb_W = (const float*)d_in[6];
    const float* comb_b = (const float*)d_in[7];
    const float* gruwih = (const float*)d_in[8];
    const float* gruwhh = (const float*)d_in[9];
    const float* grubih = (const float*)d_in[10];
    const float* grubhh = (const float*)d_in[11];
    const float* out_W  = (const float*)d_in[12];
    const float* out_b  = (const float*)d_in[13];
    float* out = (float*)d_out;

    int dev = 0, nsm = 148;
    cudaGetDevice(&dev);
    cudaDeviceGetAttribute(&nsm, cudaDevAttrMultiProcessorCount, dev);
    int nb5 = 6 * nsm;                   // ~888-912: single wave, high occupancy
    if (nb5 > MAXNB5) nb5 = MAXNB5;
    int nb2 = (Hdim + ROWS2 - 1) / ROWS2;   // 147

    {
        void* args[] = { (void*)&inp, (void*)&hidden, (void*)&emb,
                         (void*)&attn_W, (void*)&attn_b };
        launch_pdl((void*)k1_scores, dim3(Ldim), dim3(256), args);
    }
    {
        void* args[] = { (void*)&comb_W, (void*)&comb_b, (void*)&inp,
                         (void*)&emb, (void*)&enc, (void*)&out, (void*)&out_size };
        launch_pdl((void*)k2_comb, dim3(nb2), dim3(512), args);
    }
    {
        void* args[] = { (void*)&hidden, (void*)&gruwih, (void*)&gruwhh,
                         (void*)&grubih, (void*)&grubhh, (void*)&out, (void*)&out_size };
        launch_pdl((void*)k3_gru, dim3(Hdim / UPB3), dim3(256), args);
    }
    {
        void* args[] = { (void*)&out_W, (void*)&out_b };
        launch_pdl((void*)k5_logits, dim3(nb5), dim3(256), args);
    }
    {
        void* args[] = { (void*)&out, (void*)&nb5 };
        launch_pdl((void*)k67_write, dim3(NB7), dim3(256), args);
    }
}

// round 14
// speedup vs baseline: 1.0573x; 1.0573x over previous
#include <cuda_runtime.h>
#include <cuda_bf16.h>
#include <math.h>

#define Hdim 1024
#define Ldim 10
#define Vdim 50257
#define ROWS_PER_BLK 32                                   // k5: 16 warps x 2 rows
#define NB5 ((Vdim + ROWS_PER_BLK - 1) / ROWS_PER_BLK)    // 1571
#define NB7 ((Vdim + 255) / 256)                          // 197
#define ROWS2 7      // k2: rows per block (147*7 >= 1024)
#define UPB3 2       // k3: units per block (512 blocks)

// ---- scratch (no allocations allowed) ----
__device__ __align__(16) float g_scores[Ldim];
__device__ __align__(16) float g_x[Hdim];
__device__ __align__(16) float g_hnew[Hdim];
__device__ __align__(16) float g_logits[Vdim];
__device__ float g_pmax[NB5];
__device__ float g_psum[NB5];

__device__ __forceinline__ float warp_sum(float s) {
#pragma unroll
    for (int o = 16; o; o >>= 1) s += __shfl_down_sync(0xffffffffu, s, o);
    return s;
}

__device__ __forceinline__ void lse_merge(float& m, float& s, float m2, float s2) {
    if (m2 > m) { s = s * expf(m - m2) + s2; m = m2; }
    else if (s2 > 0.f) { s += s2 * expf(m2 - m); }
}

__device__ __forceinline__ void l2_prefetch(const void* p) {
    asm volatile("prefetch.global.L2 [%0];" :: "l"(p));
}

__device__ __forceinline__ float dot4(float4 a, float4 b) {
    return a.x * b.x + a.y * b.y + a.z * b.z + a.w * b.w;
}

// K1: attention scores only. 10 blocks x 256 threads; inputs only -> no gridsync.
__global__ __launch_bounds__(256) void k1_scores(const int* __restrict__ inp,
                                                 const float* __restrict__ hidden,
                                                 const float* __restrict__ emb,
                                                 const float* __restrict__ attn_W,
                                                 const float* __restrict__ attn_b) {
    cudaTriggerProgrammaticLaunchCompletion();
    __shared__ float red[8];
    int l = blockIdx.x;
    int tid = threadIdx.x, warp = tid >> 5, lane = tid & 31;
    int tok = inp[0];
    const float4* erow = (const float4*)(emb + (size_t)tok * Hdim);
    const float4* h4 = (const float4*)hidden;
    const float4* wr = (const float4*)(attn_W + (size_t)l * 2 * Hdim);
    float4 w0 = __ldcs(wr + tid);
    float4 w1 = __ldcs(wr + 256 + tid);
    float s = dot4(w0, erow[tid]) + dot4(w1, h4[tid]);
    s = warp_sum(s);
    if (lane == 0) red[warp] = s;
    __syncthreads();
    if (tid == 0) {
        float v = red[0] + red[1] + red[2] + red[3]
                + red[4] + red[5] + red[6] + red[7];
        g_scores[l] = v + attn_b[l];
    }
}

// K2: 147 blocks x 512. Each block: softmax (regs), xcat (smem), 7 comb rows.
__global__ __launch_bounds__(512) void k2_comb(const float* __restrict__ comb_W,
                                               const float* __restrict__ comb_b,
                                               const int* __restrict__ inp,
                                               const float* __restrict__ emb,
                                               const float* __restrict__ enc,
                                               float* __restrict__ out, int out_size) {
    __shared__ __align__(16) float s_xcat[2 * Hdim];
    int tid = threadIdx.x, warp = tid >> 5, lane = tid & 31;
    int r0 = blockIdx.x * ROWS2;

    for (int i = tid; i < ROWS2 * 64; i += 512) {
        int r = r0 + i / 64;
        if (r < Hdim)
            l2_prefetch((const char*)(comb_W + (size_t)r * 2 * Hdim) + (i % 64) * 128);
    }
    if (blockIdx.x < 8)
        for (int i = tid; i < 320; i += 512)
            l2_prefetch((const char*)enc + i * 128);
    int tok = inp[0];
    if (tid < 256)
        ((float4*)s_xcat)[tid] = ((const float4*)(emb + (size_t)tok * Hdim))[tid];

    cudaTriggerProgrammaticLaunchCompletion();
    cudaGridDependencySynchronize();

    float wl[Ldim];
    {
        float sc[Ldim];
#pragma unroll
        for (int l = 0; l < Ldim; l++) sc[l] = g_scores[l];
        float m = sc[0];
#pragma unroll
        for (int l = 1; l < Ldim; l++) m = fmaxf(m, sc[l]);
        float ssum = 0.f;
#pragma unroll
        for (int l = 0; l < Ldim; l++) { wl[l] = expf(sc[l] - m); ssum += wl[l]; }
        float inv = 1.f / ssum;
#pragma unroll
        for (int l = 0; l < Ldim; l++) wl[l] *= inv;
    }
    if (blockIdx.x == 0 && tid < Ldim && out_size >= Vdim + Hdim + Ldim)
        out[Vdim + Hdim + tid] = wl[tid];

    if (tid < 256) {
        const float4* e4 = (const float4*)enc;
        float4 a = make_float4(0.f, 0.f, 0.f, 0.f);
#pragma unroll
        for (int l = 0; l < Ldim; l++) {
            float4 e = __ldg(e4 + l * 256 + tid);
            a.x += wl[l] * e.x; a.y += wl[l] * e.y;
            a.z += wl[l] * e.z; a.w += wl[l] * e.w;
        }
        ((float4*)s_xcat)[256 + tid] = a;
    }
    __syncthreads();

    if (warp < ROWS2) {
        int r = r0 + warp;
        if (r < Hdim) {
            const float4* wr = (const float4*)(comb_W + (size_t)r * 2 * Hdim);
            const float4* xc = (const float4*)s_xcat;
            float s = 0.f;
#pragma unroll
            for (int k = 0; k < 16; k++) {
                int idx = lane + 32 * k;
                s += dot4(__ldcs(wr + idx), xc[idx]);
            }
            s = warp_sum(s);
            if (lane == 0) g_x[r] = fmaxf(s + comb_b[r], 0.f);
        }
    }
}

// K3: 512 blocks x 256 threads, 2 units each. Pre-sync L2-prefetch of all rows.
__global__ __launch_bounds__(256) void k3_gru(const float* __restrict__ hidden,
                                              const float* __restrict__ wih,
                                              const float* __restrict__ whh,
                                              const float* __restrict__ bih,
                                              const float* __restrict__ bhh,
                                              float* __restrict__ out, int out_size) {
    __shared__ float red[6][8];
    int u0 = blockIdx.x * UPB3;
    int tid = threadIdx.x, warp = tid >> 5, lane = tid & 31;

    for (int i = tid; i < UPB3 * 6 * 32; i += 256) {
        int uu = i / 192;
        int rem = i % 192;
        int row6 = rem / 32;
        int line = rem % 32;
        int u = u0 + uu;
        const float* base;
        if (row6 < 3) base = wih + (size_t)(u + row6 * Hdim) * Hdim;
        else          base = whh + (size_t)(u + (row6 - 3) * Hdim) * Hdim;
        l2_prefetch((const char*)base + line * 128);
    }
    float4 hv = ((const float4*)hidden)[tid];

    cudaTriggerProgrammaticLaunchCompletion();
    cudaGridDependencySynchronize();

    float4 xv = ((const float4*)g_x)[tid];

#pragma unroll
    for (int j = 0; j < UPB3; j++) {
        int u = u0 + j;
        const float4* wir = (const float4*)(wih + (size_t)u * Hdim);
        const float4* wiz = (const float4*)(wih + (size_t)(u + Hdim) * Hdim);
        const float4* win = (const float4*)(wih + (size_t)(u + 2 * Hdim) * Hdim);
        const float4* whr = (const float4*)(whh + (size_t)u * Hdim);
        const float4* whz = (const float4*)(whh + (size_t)(u + Hdim) * Hdim);
        const float4* whn = (const float4*)(whh + (size_t)(u + 2 * Hdim) * Hdim);
        float s0 = dot4(__ldcs(wir + tid), xv);
        float s1 = dot4(__ldcs(wiz + tid), xv);
        float s2 = dot4(__ldcs(win + tid), xv);
        float s3 = dot4(__ldcs(whr + tid), hv);
        float s4 = dot4(__ldcs(whz + tid), hv);
        float s5 = dot4(__ldcs(whn + tid), hv);
        s0 = warp_sum(s0); s1 = warp_sum(s1); s2 = warp_sum(s2);
        s3 = warp_sum(s3); s4 = warp_sum(s4); s5 = warp_sum(s5);
        if (lane == 0) {
            red[0][warp] = s0; red[1][warp] = s1; red[2][warp] = s2;
            red[3][warp] = s3; red[4][warp] = s4; red[5][warp] = s5;
        }
        __syncthreads();
        if (tid == 0) {
            float g[6];
#pragma unroll
            for (int gi = 0; gi < 6; gi++) {
                float acc = 0.f;
#pragma unroll
                for (int w = 0; w < 8; w++) acc += red[gi][w];
                g[gi] = acc;
            }
            float r = 1.f / (1.f + expf(-((g[0] + bih[u]) + (g[3] + bhh[u]))));
            float z = 1.f / (1.f + expf(-((g[1] + bih[Hdim + u]) + (g[4] + bhh[Hdim + u]))));
            float n = tanhf((g[2] + bih[2 * Hdim + u]) + r * (g[5] + bhh[2 * Hdim + u]));
            float hn = (1.f - z) * n + z * hidden[u];
            g_hnew[u] = hn;
            if (out_size >= Vdim + Hdim) out[Vdim + u] = hn;
        }
        __syncthreads();
    }
}

// K5: ONE-SHOT logits (R2 shape — best measured non-pathological k5).
// 1571 blocks x 512 thr, 16 warps x 2 rows. Pre-gridsync L2 prefetch of both
// rows (register-free, idle-window only — no in-loop prefetch).
__global__ __launch_bounds__(512) void k5_logits(const float* __restrict__ outW,
                                                 const float* __restrict__ outb) {
    __shared__ __align__(16) float sh[Hdim];
    __shared__ float slog[ROWS_PER_BLK];
    int tid = threadIdx.x, warp = tid >> 5, lane = tid & 31;
    int row0 = blockIdx.x * ROWS_PER_BLK + warp * 2;
    int row1 = row0 + 1;
    bool v0 = row0 < Vdim, v1 = row1 < Vdim;
    const float4* wr0 = (const float4*)(outW + (size_t)(v0 ? row0 : 0) * Hdim);
    const float4* wr1 = (const float4*)(outW + (size_t)(v1 ? row1 : 0) * Hdim);

    // idle-window prefetch: both 4KB rows, 32 lanes x 128B each
    l2_prefetch((const char*)wr0 + lane * 128);
    l2_prefetch((const char*)wr1 + lane * 128);

    cudaTriggerProgrammaticLaunchCompletion();
    cudaGridDependencySynchronize();

    sh[tid] = g_hnew[tid];
    sh[tid + 512] = g_hnew[tid + 512];
    __syncthreads();
    const float4* hh = (const float4*)sh;

    float s0 = 0.f, s1 = 0.f;
#pragma unroll
    for (int k = 0; k < 8; k++) {
        int idx = lane + 32 * k;
        float4 h = hh[idx];
        s0 += dot4(__ldcs(wr0 + idx), h);
        s1 += dot4(__ldcs(wr1 + idx), h);
    }
    s0 = warp_sum(s0);
    s1 = warp_sum(s1);
    if (lane == 0) {
        float lg0 = v0 ? (s0 + outb[row0]) : -INFINITY;
        float lg1 = v1 ? (s1 + outb[row1]) : -INFINITY;
        if (v0) g_logits[row0] = lg0;
        if (v1) g_logits[row1] = lg1;
        slog[warp * 2] = lg0;
        slog[warp * 2 + 1] = lg1;
    }
    __syncthreads();
    if (tid == 0) {
        float m = slog[0];
#pragma unroll
        for (int w = 1; w < ROWS_PER_BLK; w++) m = fmaxf(m, slog[w]);
        float s = 0.f;
#pragma unroll
        for (int w = 0; w < ROWS_PER_BLK; w++) s += expf(slog[w] - m);
        g_pmax[blockIdx.x] = m;
        g_psum[blockIdx.x] = s;
    }
}

// K67: global logsumexp reduce (redundant per block) + output write.
__global__ __launch_bounds__(256) void k67_write(float* __restrict__ out) {
    cudaGridDependencySynchronize();
    __shared__ float sm[256], ss[256];
    int tid = threadIdx.x;
    float m = -INFINITY, s = 0.f;
    for (int b = tid; b < NB5; b += 256)
        lse_merge(m, s, g_pmax[b], g_psum[b]);
    sm[tid] = m; ss[tid] = s;
    __syncthreads();
#pragma unroll
    for (int o = 128; o; o >>= 1) {
        if (tid < o) lse_merge(sm[tid], ss[tid], sm[tid + o], ss[tid + o]);
        __syncthreads();
    }
    __shared__ float shift;
    if (tid == 0) shift = sm[0] + logf(ss[0]);
    __syncthreads();
    int v = blockIdx.x * 256 + tid;
    if (v < Vdim) out[v] = g_logits[v] - shift;
}

static inline void launch_pdl(void* func, dim3 grid, dim3 block, void** args) {
    cudaLaunchAttribute attr[1];
    attr[0].id = cudaLaunchAttributeProgrammaticStreamSerialization;
    attr[0].val.programmaticStreamSerializationAllowed = 1;
    cudaLaunchConfig_t cfg = {};
    cfg.gridDim = grid;
    cfg.blockDim = block;
    cfg.dynamicSmemBytes = 0;
    cfg.stream = 0;
    cfg.attrs = attr;
    cfg.numAttrs = 1;
    cudaLaunchKernelExC(&cfg, func, args);
}

extern "C" void kernel_launch(void* const* d_in, const int* in_sizes, int n_in,
                              void* d_out, int out_size) {
    const int*   inp    = (const int*)  d_in[0];
    const float* hidden = (const float*)d_in[1];
    const float* enc    = (const float*)d_in[2];
    const float* emb    = (const float*)d_in[3];
    const float* attn_W = (const float*)d_in[4];
    const float* attn_b = (const float*)d_in[5];
    const float* comb_W = (const float*)d_in[6];
    const float* comb_b = (const float*)d_in[7];
    const float* gruwih = (const float*)d_in[8];
    const float* gruwhh = (const float*)d_in[9];
    const float* grubih = (const float*)d_in[10];
    const float* grubhh = (const float*)d_in[11];
    const float* out_W  = (const float*)d_in[12];
    const float* out_b  = (const float*)d_in[13];
    float* out = (float*)d_out;

    int nb2 = (Hdim + ROWS2 - 1) / ROWS2;   // 147

    {
        void* args[] = { (void*)&inp, (void*)&hidden, (void*)&emb,
                         (void*)&attn_W, (void*)&attn_b };
        launch_pdl((void*)k1_scores, dim3(Ldim), dim3(256), args);
    }
    {
        void* args[] = { (void*)&comb_W, (void*)&comb_b, (void*)&inp,
                         (void*)&emb, (void*)&enc, (void*)&out, (void*)&out_size };
        launch_pdl((void*)k2_comb, dim3(nb2), dim3(512), args);
    }
    {
        void* args[] = { (void*)&hidden, (void*)&gruwih, (void*)&gruwhh,
                         (void*)&grubih, (void*)&grubhh, (void*)&out, (void*)&out_size };
        launch_pdl((void*)k3_gru, dim3(Hdim / UPB3), dim3(256), args);
    }
    {
        void* args[] = { (void*)&out_W, (void*)&out_b };
        launch_pdl((void*)k5_logits, dim3(NB5), dim3(512), args);
    }
    {
        void* args[] = { (void*)&out };
        launch_pdl((void*)k67_write, dim3(NB7), dim3(256), args);
    }
}

// round 15
// speedup vs baseline: 1.1276x; 1.0665x over previous
#include <cuda_runtime.h>
#include <cuda_bf16.h>
#include <math.h>

#define Hdim 1024
#define Ldim 10
#define Vdim 50257
#define NWARP5 16
#define MAXNB5 512
#define NB7 ((Vdim + 255) / 256)
#define ROWS2 7      // k2: rows per block (147*7 >= 1024)

// ---- scratch (no allocations allowed) ----
__device__ __align__(16) float g_x[Hdim];
__device__ __align__(16) float g_hnew[Hdim];
__device__ __align__(16) float g_logits[Vdim];
__device__ float g_pmax[MAXNB5];
__device__ float g_psum[MAXNB5];

__device__ __forceinline__ float warp_sum(float s) {
#pragma unroll
    for (int o = 16; o; o >>= 1) s += __shfl_down_sync(0xffffffffu, s, o);
    return s;
}

__device__ __forceinline__ void lse_merge(float& m, float& s, float m2, float s2) {
    if (m2 > m) { s = s * expf(m - m2) + s2; m = m2; }
    else if (s2 > 0.f) { s += s2 * expf(m2 - m); }
}

__device__ __forceinline__ void l2_prefetch(const void* p) {
    asm volatile("prefetch.global.L2 [%0];" :: "l"(p));
}

__device__ __forceinline__ float dot4(float4 a, float4 b) {
    return a.x * b.x + a.y * b.y + a.z * b.z + a.w * b.w;
}

// K2: 147 blocks x 512. NO gridsync — scores computed in-block from inputs only.
// Pre-phase: prefetch comb rows, compute 10 attention scores (warps 0..9).
// Then: softmax (regs), xcat (smem), 7 comb rows -> g_x.
__global__ __launch_bounds__(512) void k2_comb(const float* __restrict__ comb_W,
                                               const float* __restrict__ comb_b,
                                               const int* __restrict__ inp,
                                               const float* __restrict__ emb,
                                               const float* __restrict__ enc,
                                               const float* __restrict__ attn_W,
                                               const float* __restrict__ attn_b,
                                               const float* __restrict__ hidden,
                                               float* __restrict__ out, int out_size) {
    cudaTriggerProgrammaticLaunchCompletion();
    __shared__ __align__(16) float s_xcat[2 * Hdim];
    __shared__ float s_sc[Ldim];
    int tid = threadIdx.x, warp = tid >> 5, lane = tid & 31;
    int r0 = blockIdx.x * ROWS2;

    // prefetch this block's comb rows (8KB/row = 64 lines) — L2 warm
    for (int i = tid; i < ROWS2 * 64; i += 512) {
        int r = r0 + i / 64;
        if (r < Hdim)
            l2_prefetch((const char*)(comb_W + (size_t)r * 2 * Hdim) + (i % 64) * 128);
    }
    int tok = inp[0];
    const float4* erow4 = (const float4*)(emb + (size_t)tok * Hdim);
    const float4* h4 = (const float4*)hidden;

    // emb half of xcat straight to smem
    if (tid < 256)
        ((float4*)s_xcat)[tid] = erow4[tid];

    // attention scores (inputs only): warp l computes score l
    if (warp < Ldim) {
        const float4* wr = (const float4*)(attn_W + (size_t)warp * 2 * Hdim);
        float s = 0.f;
#pragma unroll
        for (int k = 0; k < 16; k++) {
            int idx = lane + 32 * k;                 // 0..511
            float4 x = (idx < 256) ? erow4[idx] : h4[idx - 256];
            s += dot4(__ldg(wr + idx), x);
        }
        s = warp_sum(s);
        if (lane == 0) s_sc[warp] = s + attn_b[warp];
    }
    __syncthreads();

    // softmax over 10 scores (register-resident, redundant per thread)
    float wl[Ldim];
    {
        float m = s_sc[0];
#pragma unroll
        for (int l = 1; l < Ldim; l++) m = fmaxf(m, s_sc[l]);
        float ssum = 0.f;
#pragma unroll
        for (int l = 0; l < Ldim; l++) { wl[l] = expf(s_sc[l] - m); ssum += wl[l]; }
        float inv = 1.f / ssum;
#pragma unroll
        for (int l = 0; l < Ldim; l++) wl[l] *= inv;
    }
    if (blockIdx.x == 0 && tid < Ldim && out_size >= Vdim + Hdim + Ldim)
        out[Vdim + Hdim + tid] = wl[tid];

    // attn half of xcat
    if (tid < 256) {
        const float4* e4 = (const float4*)enc;
        float4 a = make_float4(0.f, 0.f, 0.f, 0.f);
#pragma unroll
        for (int l = 0; l < Ldim; l++) {
            float4 e = __ldg(e4 + l * 256 + tid);
            a.x += wl[l] * e.x; a.y += wl[l] * e.y;
            a.z += wl[l] * e.z; a.w += wl[l] * e.w;
        }
        ((float4*)s_xcat)[256 + tid] = a;
    }
    __syncthreads();

    // 7 rows, one warp each; dot length 2048 = 16 f4 per lane
    if (warp < ROWS2) {
        int r = r0 + warp;
        if (r < Hdim) {
            const float4* wr = (const float4*)(comb_W + (size_t)r * 2 * Hdim);
            const float4* xc = (const float4*)s_xcat;
            float s = 0.f;
#pragma unroll
            for (int k = 0; k < 16; k++) {
                int idx = lane + 32 * k;
                s += dot4(__ldcs(wr + idx), xc[idx]);
            }
            s = warp_sum(s);
            if (lane == 0) g_x[r] = fmaxf(s + comb_b[r], 0.f);
        }
    }
}

// K3: 1024 blocks x 256 threads, ONE unit each (shortest critical path).
// Pre-sync L2-prefetch of all 6 weight rows.
__global__ __launch_bounds__(256) void k3_gru(const float* __restrict__ hidden,
                                              const float* __restrict__ wih,
                                              const float* __restrict__ whh,
                                              const float* __restrict__ bih,
                                              const float* __restrict__ bhh,
                                              float* __restrict__ out, int out_size) {
    __shared__ float red[6][8];
    int u = blockIdx.x;
    int tid = threadIdx.x, warp = tid >> 5, lane = tid & 31;

    const float4* wir = (const float4*)(wih + (size_t)u * Hdim);
    const float4* wiz = (const float4*)(wih + (size_t)(u + Hdim) * Hdim);
    const float4* win = (const float4*)(wih + (size_t)(u + 2 * Hdim) * Hdim);
    const float4* whr = (const float4*)(whh + (size_t)u * Hdim);
    const float4* whz = (const float4*)(whh + (size_t)(u + Hdim) * Hdim);
    const float4* whn = (const float4*)(whh + (size_t)(u + 2 * Hdim) * Hdim);

    // prefetch 6 rows x 32 lines = 192 lines
    for (int i = tid; i < 192; i += 256) {
        int row6 = i / 32, line = i % 32;
        const float* base;
        if (row6 < 3) base = wih + (size_t)(u + row6 * Hdim) * Hdim;
        else          base = whh + (size_t)(u + (row6 - 3) * Hdim) * Hdim;
        l2_prefetch((const char*)base + line * 128);
    }
    float4 hv = ((const float4*)hidden)[tid];

    cudaTriggerProgrammaticLaunchCompletion();
    cudaGridDependencySynchronize();

    float4 xv = ((const float4*)g_x)[tid];
    float s0 = dot4(__ldcs(wir + tid), xv);
    float s1 = dot4(__ldcs(wiz + tid), xv);
    float s2 = dot4(__ldcs(win + tid), xv);
    float s3 = dot4(__ldcs(whr + tid), hv);
    float s4 = dot4(__ldcs(whz + tid), hv);
    float s5 = dot4(__ldcs(whn + tid), hv);
    s0 = warp_sum(s0); s1 = warp_sum(s1); s2 = warp_sum(s2);
    s3 = warp_sum(s3); s4 = warp_sum(s4); s5 = warp_sum(s5);
    if (lane == 0) {
        red[0][warp] = s0; red[1][warp] = s1; red[2][warp] = s2;
        red[3][warp] = s3; red[4][warp] = s4; red[5][warp] = s5;
    }
    __syncthreads();
    if (tid == 0) {
        float g[6];
#pragma unroll
        for (int gi = 0; gi < 6; gi++) {
            float acc = 0.f;
#pragma unroll
            for (int w = 0; w < 8; w++) acc += red[gi][w];
            g[gi] = acc;
        }
        float r = 1.f / (1.f + expf(-((g[0] + bih[u]) + (g[3] + bhh[u]))));
        float z = 1.f / (1.f + expf(-((g[1] + bih[Hdim + u]) + (g[4] + bhh[Hdim + u]))));
        float n = tanhf((g[2] + bih[2 * Hdim + u]) + r * (g[5] + bhh[2 * Hdim + u]));
        float hn = (1.f - z) * n + z * hidden[u];
        g_hnew[u] = hn;
        if (out_size >= Vdim + Hdim) out[Vdim + u] = hn;
    }
}

// K5: PERSISTENT logits + per-block (max,sumexp). One wave: grid = 2*SMs.
// (R10 config — best measured total.)
__global__ __launch_bounds__(512, 2) void k5_logits(const float* __restrict__ outW,
                                                    const float* __restrict__ outb) {
    __shared__ __align__(16) float sh[Hdim];
    __shared__ float sm[NWARP5], ss[NWARP5];
    int tid = threadIdx.x, warp = tid >> 5, lane = tid & 31;

    int per = (Vdim + gridDim.x - 1) / gridDim.x;
    int start = blockIdx.x * per;
    int end = start + per; if (end > Vdim) end = Vdim;

    {   // warm L2 with this warp's first two rows while predecessors run
        int r0 = start + 2 * warp;
        if (r0 < end) {
            l2_prefetch((const char*)(outW + (size_t)r0 * Hdim) + lane * 128);
            if (r0 + 1 < end)
                l2_prefetch((const char*)(outW + (size_t)(r0 + 1) * Hdim) + lane * 128);
        }
    }
    cudaTriggerProgrammaticLaunchCompletion();
    cudaGridDependencySynchronize();

    sh[tid] = g_hnew[tid];
    sh[tid + 512] = g_hnew[tid + 512];
    __syncthreads();
    const float4* hh = (const float4*)sh;

    float m = -INFINITY, ssum = 0.f;
    for (int r = start + 2 * warp; r < end; r += 2 * NWARP5) {
        int r1 = r + 1;
        bool v1 = r1 < end;
        const float4* w0 = (const float4*)(outW + (size_t)r * Hdim);
        const float4* w1 = (const float4*)(outW + (size_t)(v1 ? r1 : r) * Hdim);
        float a0 = 0.f, a1 = 0.f;
#pragma unroll
        for (int k = 0; k < 8; k++) {
            int idx = lane + 32 * k;
            float4 h = hh[idx];
            a0 += dot4(__ldcs(w0 + idx), h);
            a1 += dot4(__ldcs(w1 + idx), h);
        }
        a0 = warp_sum(a0);
        a1 = warp_sum(a1);
        if (lane == 0) {
            float lg0 = a0 + outb[r];
            g_logits[r] = lg0;
            lse_merge(m, ssum, lg0, 1.f);
            if (v1) {
                float lg1 = a1 + outb[r1];
                g_logits[r1] = lg1;
                lse_merge(m, ssum, lg1, 1.f);
            }
        }
    }
    if (lane == 0) { sm[warp] = m; ss[warp] = ssum; }
    __syncthreads();
    if (tid == 0) {
        float gm = -INFINITY, gs = 0.f;
#pragma unroll
        for (int w = 0; w < NWARP5; w++) lse_merge(gm, gs, sm[w], ss[w]);
        g_pmax[blockIdx.x] = gm;
        g_psum[blockIdx.x] = gs;
    }
}

// K67: global logsumexp reduce (redundant per block) + output write.
__global__ __launch_bounds__(256) void k67_write(float* __restrict__ out, int nb5) {
    cudaGridDependencySynchronize();
    __shared__ float sm[256], ss[256];
    int tid = threadIdx.x;
    float m = -INFINITY, s = 0.f;
    for (int b = tid; b < nb5; b += 256)
        lse_merge(m, s, g_pmax[b], g_psum[b]);
    sm[tid] = m; ss[tid] = s;
    __syncthreads();
#pragma unroll
    for (int o = 128; o; o >>= 1) {
        if (tid < o) lse_merge(sm[tid], ss[tid], sm[tid + o], ss[tid + o]);
        __syncthreads();
    }
    __shared__ float shift;
    if (tid == 0) shift = sm[0] + logf(ss[0]);
    __syncthreads();
    int v = blockIdx.x * 256 + tid;
    if (v < Vdim) out[v] = g_logits[v] - shift;
}

static inline void launch_pdl(void* func, dim3 grid, dim3 block, void** args) {
    cudaLaunchAttribute attr[1];
    attr[0].id = cudaLaunchAttributeProgrammaticStreamSerialization;
    attr[0].val.programmaticStreamSerializationAllowed = 1;
    cudaLaunchConfig_t cfg = {};
    cfg.gridDim = grid;
    cfg.blockDim = block;
    cfg.dynamicSmemBytes = 0;
    cfg.stream = 0;
    cfg.attrs = attr;
    cfg.numAttrs = 1;
    cudaLaunchKernelExC(&cfg, func, args);
}

extern "C" void kernel_launch(void* const* d_in, const int* in_sizes, int n_in,
                              void* d_out, int out_size) {
    const int*   inp    = (const int*)  d_in[0];
    const float* hidden = (const float*)d_in[1];
    const float* enc    = (const float*)d_in[2];
    const float* emb    = (const float*)d_in[3];
    const float* attn_W = (const float*)d_in[4];
    const float* attn_b = (const float*)d_in[5];
    const float* comb_W = (const float*)d_in[6];
    const float* comb_b = (const float*)d_in[7];
    const float* gruwih = (const float*)d_in[8];
    const float* gruwhh = (const float*)d_in[9];
    const float* grubih = (const float*)d_in[10];
    const float* grubhh = (const float*)d_in[11];
    const float* out_W  = (const float*)d_in[12];
    const float* out_b  = (const float*)d_in[13];
    float* out = (float*)d_out;

    int dev = 0, nsm = 148;
    cudaGetDevice(&dev);
    cudaDeviceGetAttribute(&nsm, cudaDevAttrMultiProcessorCount, dev);
    int nb5 = 2 * nsm;                       // R10's best k5 grid
    if (nb5 > MAXNB5) nb5 = MAXNB5;
    int nb2 = (Hdim + ROWS2 - 1) / ROWS2;    // 147

    {   // k2 has no dependencies (scores computed in-block from inputs)
        void* args[] = { (void*)&comb_W, (void*)&comb_b, (void*)&inp,
                         (void*)&emb, (void*)&enc, (void*)&attn_W, (void*)&attn_b,
                         (void*)&hidden, (void*)&out, (void*)&out_size };
        launch_pdl((void*)k2_comb, dim3(nb2), dim3(512), args);
    }
    {
        void* args[] = { (void*)&hidden, (void*)&gruwih, (void*)&gruwhh,
                         (void*)&grubih, (void*)&grubhh, (void*)&out, (void*)&out_size };
        launch_pdl((void*)k3_gru, dim3(Hdim), dim3(256), args);
    }
    {
        void* args[] = { (void*)&out_W, (void*)&out_b };
        launch_pdl((void*)k5_logits, dim3(nb5), dim3(512), args);
    }
    {
        void* args[] = { (void*)&out, (void*)&nb5 };
        launch_pdl((void*)k67_write, dim3(NB7), dim3(256), args);
    }
}